// round 7
// baseline (speedup 1.0000x reference)
#include <cuda_runtime.h>
#include <cstdint>

#define MAXN 100000
#define DD 64
#define GRID1 592   // grid for both GEMM kernels (4 waves of 148)

// ---- scratch (no allocations allowed) ----
__device__ __align__(16) float  g_hbuf[(size_t)MAXN * DD];   // h = (1+eps)*x + scatter [N,64]
__device__ __align__(16) float  g_h1[(size_t)MAXN * 2 * DD]; // pre-BN hidden           [N,128]
__device__ float  g_psum[GRID1 * 128];                       // per-block BN partials
__device__ float  g_psq [GRID1 * 128];
__device__ float  g_scale[2 * DD];
__device__ float  g_shift[2 * DD];
__device__ int    g_is64;                                    // 1 if edge buffers are int64

// ---------------------------------------------------------------------------
// K0: dtype probe. edge_feats values are tiny (0/1). Read 32 int64 words:
// if all in [0,7] -> data really is int64; else it was downcast to int32.
// ---------------------------------------------------------------------------
__global__ void k_probe(const long long* __restrict__ ef)
{
    int ok = 1;
#pragma unroll
    for (int i = 0; i < 32; i++) {
        long long v = ef[i];
        if (v < 0 || v > 7) ok = 0;
    }
    g_is64 = ok;
}

// ---------------------------------------------------------------------------
// K1: h = (1+eps)*node_feats
// ---------------------------------------------------------------------------
__global__ void k_init(const float* __restrict__ nf, const float* __restrict__ eps, int n4)
{
    int i = blockIdx.x * blockDim.x + threadIdx.x;
    if (i < n4) {
        float s = 1.0f + eps[0];
        float4 v = ((const float4*)nf)[i];
        v.x *= s; v.y *= s; v.z *= s; v.w *= s;
        ((float4*)g_hbuf)[i] = v;
    }
}

// ---------------------------------------------------------------------------
// K2: edge messages + scatter-add.  2 edges per warp, 16 lanes x float4 each.
// ---------------------------------------------------------------------------
__global__ void k_edge(const float4* __restrict__ nf4,
                       const void* __restrict__ ef,    // [E,3]
                       const void* __restrict__ ei,    // [2,E]: row0=dst, row1=src
                       const float4* __restrict__ e0,
                       const float4* __restrict__ e1,
                       const float4* __restrict__ e2,
                       long long E, int Nn)
{
    int lane = threadIdx.x & 31;
    long long warpId = (long long)blockIdx.x * (blockDim.x >> 5) + (threadIdx.x >> 5);
    int half = lane >> 4;
    int q    = lane & 15;
    long long e = warpId * 2 + half;

    int src = 0, dst = 0, f0 = 0, f1 = 0, f2 = 0;
    if (q == 0 && e < E) {
        if (g_is64) {
            const long long* ei64 = (const long long*)ei;
            const long long* ef64 = (const long long*)ef + e * 3;
            dst = (int)ei64[e];
            src = (int)ei64[E + e];
            f0 = (int)ef64[0]; f1 = (int)ef64[1]; f2 = (int)ef64[2];
        } else {
            const int* ei32 = (const int*)ei;
            const int* ef32 = (const int*)ef + e * 3;
            dst = ei32[e];
            src = ei32[E + e];
            f0 = ef32[0]; f1 = ef32[1]; f2 = ef32[2];
        }
    }
    int leader = half << 4;
    dst = __shfl_sync(0xffffffffu, dst, leader);
    src = __shfl_sync(0xffffffffu, src, leader);
    f0  = __shfl_sync(0xffffffffu, f0,  leader);
    f1  = __shfl_sync(0xffffffffu, f1,  leader);
    f2  = __shfl_sync(0xffffffffu, f2,  leader);
    if (e >= E) return;
    if ((unsigned)src >= (unsigned)Nn || (unsigned)dst >= (unsigned)Nn) return;
    if ((unsigned)f0 > 4u || (unsigned)f1 > 5u || (unsigned)f2 > 1u) return;

    float4 a = e0[f0 * 16 + q];
    float4 b = e1[f1 * 16 + q];
    float4 c = e2[f2 * 16 + q];
    float4 n = nf4[(long long)src * 16 + q];

    float x = fmaxf(n.x + a.x + b.x + c.x, 0.0f);
    float y = fmaxf(n.y + a.y + b.y + c.y, 0.0f);
    float z = fmaxf(n.z + a.z + b.z + c.z, 0.0f);
    float w = fmaxf(n.w + a.w + b.w + c.w, 0.0f);

    float* p = g_hbuf + (long long)dst * 64 + q * 4;
    asm volatile("red.global.add.v4.f32 [%0], {%1,%2,%3,%4};"
                 :: "l"(p), "f"(x), "f"(y), "f"(z), "f"(w) : "memory");
}

// ---------------------------------------------------------------------------
// K3 v3: h1 = h @ W1^T + b1 + BN partial stats.
// W row in registers; broadcast-LDS inner loop; DOUBLE-BUFFERED staging with
// prefetch (next tile's LDG issued before compute) and ONE sync per iter.
// Per-block stats go to g_psum/g_psq (no global atomics).
// ---------------------------------------------------------------------------
__global__ void __launch_bounds__(128) k_gemm1(const float* __restrict__ W1,  // [128,64]
                                               const float* __restrict__ b1,
                                               int N)
{
    __shared__ float4 hsh[2][8 * 16];  // double buffer: 8 rows x 64 floats
    int tid = threadIdx.x;
    int rowoff = tid >> 4;     // 0..7
    int kslot  = tid & 15;     // float4 slot

    float4 w[16];
#pragma unroll
    for (int k4 = 0; k4 < 16; k4++)
        w[k4] = ((const float4*)W1)[tid * 16 + k4];
    float bj = __ldg(b1 + tid);

    float lsum = 0.0f, lsq = 0.0f;

    long long step = (long long)GRID1 * 8;
    long long r0 = (long long)blockIdx.x * 8;

    // prefetch tile 0
    float4 v = make_float4(0.f, 0.f, 0.f, 0.f);
    if (r0 + rowoff < N) v = ((const float4*)g_hbuf)[(r0 + rowoff) * 16 + kslot];

    int buf = 0;
    for (; r0 < N; r0 += step) {
        hsh[buf][tid] = v;
        __syncthreads();

        // prefetch next tile (overlaps with compute below)
        long long rn = r0 + step;
        if (rn + rowoff < N) v = ((const float4*)g_hbuf)[(rn + rowoff) * 16 + kslot];
        else                 v = make_float4(0.f, 0.f, 0.f, 0.f);

        float acc[8];
#pragma unroll
        for (int r = 0; r < 8; r++) acc[r] = bj;
#pragma unroll
        for (int k4 = 0; k4 < 16; k4++) {
            float4 wv = w[k4];
#pragma unroll
            for (int r = 0; r < 8; r++) {
                float4 h = hsh[buf][r * 16 + k4];
                acc[r] += wv.x * h.x + wv.y * h.y + wv.z * h.z + wv.w * h.w;
            }
        }

        long long base = r0 * 128 + tid;
#pragma unroll
        for (int r = 0; r < 8; r++) {
            if (r0 + r < N) {
                float a = acc[r];
                g_h1[base + r * 128] = a;
                lsum += a; lsq += a * a;
            }
        }
        buf ^= 1;
        // single sync per iteration: next STS targets the OTHER buffer, whose
        // last readers finished before passing the barrier above.
    }
    g_psum[blockIdx.x * 128 + tid] = lsum;
    g_psq [blockIdx.x * 128 + tid] = lsq;
}

// ---------------------------------------------------------------------------
// K4 v2: reduce per-block partials, fold BN into scale/shift. 1024 threads.
// ---------------------------------------------------------------------------
__global__ void __launch_bounds__(1024) k_bn(const float* __restrict__ gamma,
                                             const float* __restrict__ beta,
                                             double invN, int nblocks)
{
    __shared__ float ss[8][128];
    __shared__ float qq[8][128];
    int j = threadIdx.x & 127;
    int c = threadIdx.x >> 7;   // 0..7

    float s = 0.f, q = 0.f;
    for (int b = c; b < nblocks; b += 8) {
        s += g_psum[b * 128 + j];
        q += g_psq [b * 128 + j];
    }
    ss[c][j] = s; qq[c][j] = q;
    __syncthreads();

    if (threadIdx.x < 128) {
        double S = 0.0, Q = 0.0;
#pragma unroll
        for (int cc = 0; cc < 8; cc++) { S += ss[cc][j]; Q += qq[cc][j]; }
        float mean = (float)(S * invN);
        float var  = (float)(Q * invN) - mean * mean;
        float inv  = rsqrtf(var + 1e-5f);
        float sc   = gamma[j] * inv;
        g_scale[j] = sc;
        g_shift[j] = beta[j] - mean * sc;
    }
}

// ---------------------------------------------------------------------------
// K5 v3: out = relu(scale*h1 + shift) @ W2^T + b2.
// i = tid&63 (channel), hh = tid>>6 (warp-uniform K-half). Single smem buffer
// (safe: 2 syncs/iter), staging LDG prefetched across the compute phase.
// ---------------------------------------------------------------------------
__global__ void __launch_bounds__(128) k_gemm2(const float* __restrict__ W2,  // [64,128]
                                               const float* __restrict__ b2,
                                               float* __restrict__ out,
                                               int N)
{
    __shared__ float4 ash[8 * 32];      // 8 rows x 128 activations
    __shared__ float  sc[128], sh[128];
    __shared__ float  partial[8 * 64];
    int tid = threadIdx.x;
    int i  = tid & 63;
    int hh = tid >> 6;

    float4 w[16];
#pragma unroll
    for (int k4 = 0; k4 < 16; k4++)
        w[k4] = ((const float4*)W2)[i * 32 + hh * 16 + k4];
    sc[tid] = g_scale[tid];
    sh[tid] = g_shift[tid];
    float bi = __ldg(b2 + i);
    __syncthreads();

    long long step = (long long)GRID1 * 8;
    long long r0 = (long long)blockIdx.x * 8;

    // prefetch tile 0 (raw h1; scale/relu applied at STS time)
    float4 v[2];
#pragma unroll
    for (int t = 0; t < 2; t++) {
        int idx = tid + t * 128;
        long long row = r0 + (idx >> 5);
        v[t] = (row < N) ? ((const float4*)g_h1)[row * 32 + (idx & 31)]
                         : make_float4(0.f, 0.f, 0.f, 0.f);
    }

    for (; r0 < N; r0 += step) {
#pragma unroll
        for (int t = 0; t < 2; t++) {
            int idx = tid + t * 128;
            int j = (idx & 31) * 4;
            float4 a;
            a.x = fmaxf(fmaf(sc[j + 0], v[t].x, sh[j + 0]), 0.0f);
            a.y = fmaxf(fmaf(sc[j + 1], v[t].y, sh[j + 1]), 0.0f);
            a.z = fmaxf(fmaf(sc[j + 2], v[t].z, sh[j + 2]), 0.0f);
            a.w = fmaxf(fmaf(sc[j + 3], v[t].w, sh[j + 3]), 0.0f);
            ash[idx] = a;
        }
        __syncthreads();

        // prefetch next tile
        long long rn = r0 + step;
#pragma unroll
        for (int t = 0; t < 2; t++) {
            int idx = tid + t * 128;
            long long row = rn + (idx >> 5);
            v[t] = (row < N) ? ((const float4*)g_h1)[row * 32 + (idx & 31)]
                             : make_float4(0.f, 0.f, 0.f, 0.f);
        }

        float acc[8];
#pragma unroll
        for (int r = 0; r < 8; r++) acc[r] = 0.0f;
#pragma unroll
        for (int k4 = 0; k4 < 16; k4++) {
            float4 wv = w[k4];
#pragma unroll
            for (int r = 0; r < 8; r++) {
                float4 h = ash[r * 32 + hh * 16 + k4];  // warp-uniform: broadcast
                acc[r] += wv.x * h.x + wv.y * h.y + wv.z * h.z + wv.w * h.w;
            }
        }

        if (hh == 1) {
#pragma unroll
            for (int r = 0; r < 8; r++) partial[r * 64 + i] = acc[r];
        }
        __syncthreads();
        if (hh == 0) {
#pragma unroll
            for (int r = 0; r < 8; r++) {
                if (r0 + r < N)
                    out[(r0 + r) * 64 + i] = acc[r] + partial[r * 64 + i] + bi;
            }
        }
    }
}

// ---------------------------------------------------------------------------
// Binding: size-driven anchor on the unique size-320 buffer (bond_emb0).
// ---------------------------------------------------------------------------
extern "C" void kernel_launch(void* const* d_in, const int* in_sizes, int n_in,
                              void* d_out, int out_size)
{
    const float* nf = (const float*)d_in[0];
    const void*  ef = d_in[1];
    const void*  ei = d_in[2];

    int iEmb0 = -1;
    for (int i = 3; i < n_in; i++) {
        if (in_sizes[i] == 320) { iEmb0 = i; break; }
    }
    if (iEmb0 < 0) iEmb0 = 6;

    const float* eps   = (const float*)d_in[iEmb0 - 1];
    const float* e0    = (const float*)d_in[iEmb0];
    const float* e1    = (const float*)d_in[iEmb0 + 1];
    const float* e2    = (const float*)d_in[iEmb0 + 2];
    const float* W1    = (const float*)d_in[iEmb0 + 3];
    const float* b1    = (const float*)d_in[iEmb0 + 4];
    const float* gamma = (const float*)d_in[iEmb0 + 5];
    const float* beta  = (const float*)d_in[iEmb0 + 6];
    const float* W2    = (const float*)d_in[iEmb0 + 7];
    const float* b2    = (const float*)d_in[iEmb0 + 8];

    int N = in_sizes[0] / 64;
    long long E = (long long)in_sizes[1] / 3;

    k_probe<<<1, 1>>>((const long long*)ef);

    int n4 = N * 16;
    k_init<<<(n4 + 255) / 256, 256>>>(nf, eps, n4);

    long long warpsNeeded = (E + 1) / 2;
    int eblocks = (int)((warpsNeeded + 7) / 8);
    k_edge<<<eblocks, 256>>>((const float4*)nf, ef, ei,
                             (const float4*)e0, (const float4*)e1, (const float4*)e2, E, N);

    k_gemm1<<<GRID1, 128>>>(W1, b1, N);
    k_bn<<<1, 1024>>>(gamma, beta, 1.0 / (double)N, GRID1);
    k_gemm2<<<GRID1, 128>>>(W2, b2, (float*)d_out, N);
}